// round 16
// baseline (speedup 1.0000x reference)
#include <cuda_runtime.h>
#include <cuda_bf16.h>
#include <cuda_fp16.h>
#include <cstdint>

// ---------------------------------------------------------------------------
// Problem dims
// ---------------------------------------------------------------------------
#define B_DIM 64
#define S_DIM 2048
#define H_DIM 512
#define M_DIM (B_DIM * S_DIM)   // 131072
#define NEG_INF_SCORE (-1e9f)

// GEMM tiling: CTA 128x128, K chunks of 64, 16 warps (4m x 4n), warp 32x32
#define KC 64
#define NKCH (H_DIM / KC)        // 8
#define MT 128
#define NT 128
#define NTILES (H_DIM / NT)      // 4
#define NMTILES (M_DIM / MT)     // 1024
#define NSTAGE 3

// SMEM stage layout (bytes): A fp16 16KB, B fp16 16KB
#define A_OFF 0
#define B_OFF 16384
#define STAGE 32768
#define GEMM_SMEM (NSTAGE * STAGE)   // 96 KB -> 2 CTAs/SM

// Context s-chunking
#define SCHUNK 32
#define S_PER_CHUNK (S_DIM / SCHUNK)  // 64

// ---------------------------------------------------------------------------
// Device scratch (static only).
// g_Wh / g_Xh: fp16 pre-swizzled tiles, 128 rows x 64 k each, 16 KB,
// SW128-swizzled 128B rows. X tile (t, c) at index (t*8 + c).
// ---------------------------------------------------------------------------
__device__ __align__(16) __half g_Wh[H_DIM * H_DIM];
__device__ __align__(16) __half g_Xh[(size_t)M_DIM * H_DIM];   // 128 MB
__device__ float g_score_part[NTILES * M_DIM];
__device__ __align__(16) float g_ctx_part[SCHUNK * B_DIM * H_DIM];

__device__ __forceinline__ uint32_t smem_u32(const void* p) {
    uint32_t a;
    asm("{ .reg .u64 t; cvta.to.shared.u64 t, %1; cvt.u32.u64 %0, t; }" : "=r"(a) : "l"(p));
    return a;
}
// SW128 swizzle of (row-byte-base, column-byte-offset<128). Exact and in-bounds.
__device__ __forceinline__ uint32_t swz(uint32_t rowoff, uint32_t col) {
    return rowoff + (col ^ ((rowoff >> 3) & 0x70));
}

__device__ __forceinline__ void cp_async16(uint32_t dst, const void* src) {
    asm volatile("cp.async.cg.shared.global [%0], [%1], 16;"
                 :: "r"(dst), "l"(__cvta_generic_to_global(src)) : "memory");
}
__device__ __forceinline__ void cp_async_commit() {
    asm volatile("cp.async.commit_group;" ::: "memory");
}

__device__ __forceinline__ void ldsm_x4(uint32_t* r, uint32_t addr) {
    asm volatile("ldmatrix.sync.aligned.m8n8.x4.shared.b16 {%0,%1,%2,%3}, [%4];"
                 : "=r"(r[0]), "=r"(r[1]), "=r"(r[2]), "=r"(r[3]) : "r"(addr));
}

__device__ __forceinline__ void mma16816(float* d, const uint32_t* a, uint32_t b0, uint32_t b1) {
    asm volatile(
        "mma.sync.aligned.m16n8k16.row.col.f32.f16.f16.f32 "
        "{%0,%1,%2,%3}, {%4,%5,%6,%7}, {%8,%9}, {%0,%1,%2,%3};"
        : "+f"(d[0]), "+f"(d[1]), "+f"(d[2]), "+f"(d[3])
        : "r"(a[0]), "r"(a[1]), "r"(a[2]), "r"(a[3]), "r"(b0), "r"(b1));
}

// pack 2 floats -> one fp16x2 register
__device__ __forceinline__ uint32_t pack_h2(float x, float y) {
    __half2 h = __floats2half2_rn(x, y);
    return *reinterpret_cast<uint32_t*>(&h);
}

// ---------------------------------------------------------------------------
// Combined pre-convert: W (blocks 0..31) and X (blocks 32..32+8191) ->
// pre-swizzled fp16 tiles. 256 threads. One launch instead of two.
// ---------------------------------------------------------------------------
__global__ void __launch_bounds__(256)
convert_wx_kernel(const float* __restrict__ W, const float* __restrict__ X)
{
    const int id  = blockIdx.x;
    const int tid = threadIdx.x;
    const int row = tid >> 1;              // 0..127 (row within tile)
    const int kh  = (tid & 1) * 32;        // k element offset half-row

    const float* src;
    char* dst;
    if (id < NTILES * NKCH) {              // W tile (nt, c)
        const int nt = id >> 3;
        const int c  = id & 7;
        src = W + (size_t)(nt * NT + row) * H_DIM + c * KC + kh;
        dst = (char*)g_Wh + (size_t)id * 16384;
    } else {                               // X tile (t, c)
        const int idx = id - NTILES * NKCH;
        const int t = idx >> 3;
        const int c = idx & 7;
        src = X + (size_t)(t * MT + row) * H_DIM + c * KC + kh;
        dst = (char*)g_Xh + (size_t)idx * 16384;
    }

    const uint32_t rowoff = (uint32_t)row * 128;
    #pragma unroll
    for (int i = 0; i < 8; i++) {
        float4 xv = *(const float4*)(src + i * 4);
        uint2 hv;
        hv.x = pack_h2(xv.x, xv.y);
        hv.y = pack_h2(xv.z, xv.w);
        const uint32_t off = swz(rowoff, (uint32_t)(kh * 2 + i * 8));
        *(uint2*)(dst + off) = hv;
    }
}

// ---------------------------------------------------------------------------
// Scores GEMM via mma.sync fp16 (single term, fp32 accum), fused tanh.v
// reduce. A and B both pre-converted fp16, pure cp.async mainloop.
// grid (4 n-tiles, 1024 m-tiles) nt-fast for X L2 reuse.
// 512 threads / 16 warps, 3-stage pipeline, 2 CTAs/SM.
// ---------------------------------------------------------------------------
__global__ void __launch_bounds__(512, 2)
scores_gemm_mma(const float* __restrict__ bias,
                const float* __restrict__ v)
{
    extern __shared__ char smem[];
    __shared__ float red[4][MT];

    const uint32_t sb = smem_u32(smem);
    const int tid  = threadIdx.x;
    const int wid  = tid >> 5;
    const int lane = tid & 31;
    const int wm   = wid & 3;      // warp m index (0..3)
    const int wn   = wid >> 2;     // warp n index (0..3)
    const int nt = blockIdx.x;     // n-tile (fast dim -> adjacent CTAs share X)
    const int t  = blockIdx.y;     // m-tile

    // A/B global tiles (pre-swizzled 16KB blobs)
    const char* ag = (const char*)g_Xh + (size_t)(t * NKCH) * 16384;
    const char* bg = (const char*)g_Wh + (size_t)(nt * NKCH) * 16384;

    // ldmatrix row bases; column = kb + ks*32 composed inside the swizzle
    const int lrow = lane & 15;
    const uint32_t kb = (lane >> 4) * 16;
    uint32_t a_rowb[2], b_rowb[2];
    #pragma unroll
    for (int mi = 0; mi < 2; mi++)
        a_rowb[mi] = (uint32_t)(wm * 32 + mi * 16 + lrow) * 128;
    #pragma unroll
    for (int np = 0; np < 2; np++)
        b_rowb[np] = (uint32_t)(wn * 32 + np * 16 + lrow) * 128;

    float acc[2][4][4];
    #pragma unroll
    for (int mi = 0; mi < 2; mi++)
        #pragma unroll
        for (int ni = 0; ni < 4; ni++)
            #pragma unroll
            for (int j = 0; j < 4; j++) acc[mi][ni][j] = 0.f;

    // cp.async A+B for chunk c into stage c%3 (one commit group per chunk)
    auto ab_load = [&](int c) {
        const uint32_t stb = sb + (uint32_t)(c % NSTAGE) * STAGE;
        const char* ah = ag + (size_t)c * 16384;
        const char* bh = bg + (size_t)c * 16384;
        #pragma unroll
        for (int it = 0; it < 2; it++) {
            cp_async16(stb + A_OFF + tid * 16 + it * 8192, ah + tid * 16 + it * 8192);
            cp_async16(stb + B_OFF + tid * 16 + it * 8192, bh + tid * 16 + it * 8192);
        }
        cp_async_commit();
    };

    // ---- prologue: chunks 0, 1 ----
    ab_load(0);
    ab_load(1);

    for (int c = 0; c < NKCH; c++) {
        if (c == NKCH - 1) asm volatile("cp.async.wait_group 0;" ::: "memory");
        else               asm volatile("cp.async.wait_group 1;" ::: "memory");
        __syncthreads();

        if (c + 2 < NKCH)
            ab_load(c + 2);     // async, overlaps compute below; stage free

        // ---- compute chunk c ----
        const uint32_t st = sb + (uint32_t)(c % NSTAGE) * STAGE;
        #pragma unroll
        for (int ks = 0; ks < KC / 16; ks++) {
            const uint32_t kcol = kb + ks * 32;   // < 128, composed into swizzle
            uint32_t ah[2][4], bh[2][4];
            #pragma unroll
            for (int mi = 0; mi < 2; mi++)
                ldsm_x4(ah[mi], st + A_OFF + swz(a_rowb[mi], kcol));
            #pragma unroll
            for (int np = 0; np < 2; np++)
                ldsm_x4(bh[np], st + B_OFF + swz(b_rowb[np], kcol));
            #pragma unroll
            for (int mi = 0; mi < 2; mi++)
                #pragma unroll
                for (int np = 0; np < 2; np++)
                    #pragma unroll
                    for (int hf = 0; hf < 2; hf++)
                        mma16816(acc[mi][np * 2 + hf], ah[mi],
                                 bh[np][hf], bh[np][hf + 2]);
        }
    }

    // ---- epilogue: rsum[row] = sum_n v[n]*tanh(acc + b[n]) ----
    const int ncol0 = nt * NT + wn * 32 + (lane & 3) * 2;
    float rs[2][2] = {{0.f, 0.f}, {0.f, 0.f}};
    #pragma unroll
    for (int np = 0; np < 2; np++) {
        #pragma unroll
        for (int hf = 0; hf < 2; hf++) {
            #pragma unroll
            for (int cc = 0; cc < 2; cc++) {
                const int col = ncol0 + np * 16 + hf * 8 + cc;
                const float bb = bias[col];
                const float vv = v[col];
                #pragma unroll
                for (int mi = 0; mi < 2; mi++) {
                    float x0 = acc[mi][np * 2 + hf][cc] + bb;       // row groupID
                    float x1 = acc[mi][np * 2 + hf][cc + 2] + bb;   // row groupID+8
                    float t0, t1;
                    asm("tanh.approx.f32 %0, %1;" : "=f"(t0) : "f"(x0));
                    asm("tanh.approx.f32 %0, %1;" : "=f"(t1) : "f"(x1));
                    rs[mi][0] = fmaf(t0, vv, rs[mi][0]);
                    rs[mi][1] = fmaf(t1, vv, rs[mi][1]);
                }
            }
        }
    }
    // reduce across the 4 lanes sharing a row (lane bits 0-1)
    #pragma unroll
    for (int mi = 0; mi < 2; mi++)
        #pragma unroll
        for (int h = 0; h < 2; h++) {
            rs[mi][h] += __shfl_xor_sync(0xffffffffu, rs[mi][h], 1);
            rs[mi][h] += __shfl_xor_sync(0xffffffffu, rs[mi][h], 2);
        }

    __syncthreads();   // all compute done before red[] use
    if ((lane & 3) == 0) {
        #pragma unroll
        for (int mi = 0; mi < 2; mi++)
            #pragma unroll
            for (int h = 0; h < 2; h++)
                red[wn][wm * 32 + mi * 16 + h * 8 + (lane >> 2)] = rs[mi][h];
    }
    __syncthreads();
    if (tid < MT) {
        float s = red[0][tid] + red[1][tid] + red[2][tid] + red[3][tid];
        g_score_part[(size_t)nt * M_DIM + (size_t)t * MT + tid] = s;
    }
}

// ---------------------------------------------------------------------------
// Softmax (folds 4 n-tile partials), mask as int32
// ---------------------------------------------------------------------------
__device__ __forceinline__ float warp_max(float v) {
    #pragma unroll
    for (int o = 16; o > 0; o >>= 1) v = fmaxf(v, __shfl_xor_sync(0xffffffffu, v, o));
    return v;
}
__device__ __forceinline__ float warp_sum(float v) {
    #pragma unroll
    for (int o = 16; o > 0; o >>= 1) v += __shfl_xor_sync(0xffffffffu, v, o);
    return v;
}

__global__ void __launch_bounds__(256)
softmax_kernel(const int* __restrict__ mask, float* __restrict__ weights)
{
    const int b    = blockIdx.x;
    const int tid  = threadIdx.x;
    const int lane = tid & 31;
    const int wid  = tid >> 5;

    __shared__ float red[8];

    float vals[8];
    float mx = -3.4e38f;
    #pragma unroll
    for (int i = 0; i < 8; i++) {
        const size_t m = (size_t)b * S_DIM + tid + i * 256;
        float sc = 0.f;
        #pragma unroll
        for (int n = 0; n < NTILES; n++)
            sc += g_score_part[(size_t)n * M_DIM + m];
        if (mask[m] == 0) sc = NEG_INF_SCORE;
        vals[i] = sc;
        mx = fmaxf(mx, sc);
    }

    mx = warp_max(mx);
    if (lane == 0) red[wid] = mx;
    __syncthreads();
    float bmax = red[0];
    #pragma unroll
    for (int i = 1; i < 8; i++) bmax = fmaxf(bmax, red[i]);
    __syncthreads();

    float s_sum = 0.f;
    #pragma unroll
    for (int i = 0; i < 8; i++) {
        vals[i] = __expf(vals[i] - bmax);
        s_sum += vals[i];
    }
    s_sum = warp_sum(s_sum);
    if (lane == 0) red[wid] = s_sum;
    __syncthreads();
    float total = red[0];
    #pragma unroll
    for (int i = 1; i < 8; i++) total += red[i];

    const float inv = 1.0f / total;
    #pragma unroll
    for (int i = 0; i < 8; i++)
        weights[(size_t)b * S_DIM + tid + i * 256] = vals[i] * inv;
}

// ---------------------------------------------------------------------------
// Context: weighted sum over S, reading the pre-converted fp16 X tiles
// (halves DRAM traffic vs fp32 hidden). Block (sc, b), 128 threads.
// ---------------------------------------------------------------------------
__global__ void __launch_bounds__(128)
context_part_kernel(const float* __restrict__ weights)
{
    const int sc = blockIdx.x;          // 0..31
    const int b  = blockIdx.y;          // 0..63
    const int tid = threadIdx.x;
    const int th  = tid & 63;
    const int so  = tid >> 6;           // 0..1
    const int h8  = th * 8;             // h offset, step 8
    const int c   = h8 >> 6;            // k-chunk 0..7
    const uint32_t colb = (uint32_t)((h8 & 63) * 2);   // 0..112, 16B aligned

    const float* wrow = weights + (size_t)b * S_DIM + sc * S_PER_CHUNK;

    float acc[8];
    #pragma unroll
    for (int j = 0; j < 8; j++) acc[j] = 0.f;

    for (int i = so; i < S_PER_CHUNK; i += 2) {
        const int m   = b * S_DIM + sc * S_PER_CHUNK + i;
        const int t   = m >> 7;
        const int row = m & 127;
        const char* tile = (const char*)g_Xh + ((size_t)(t * NKCH + c)) * 16384;
        uint4 hv = *(const uint4*)(tile + swz((uint32_t)row * 128, colb));
        const float w = wrow[i];

        float2 f0 = __half22float2(*reinterpret_cast<__half2*>(&hv.x));
        float2 f1 = __half22float2(*reinterpret_cast<__half2*>(&hv.y));
        float2 f2 = __half22float2(*reinterpret_cast<__half2*>(&hv.z));
        float2 f3 = __half22float2(*reinterpret_cast<__half2*>(&hv.w));
        acc[0] = fmaf(w, f0.x, acc[0]); acc[1] = fmaf(w, f0.y, acc[1]);
        acc[2] = fmaf(w, f1.x, acc[2]); acc[3] = fmaf(w, f1.y, acc[3]);
        acc[4] = fmaf(w, f2.x, acc[4]); acc[5] = fmaf(w, f2.y, acc[5]);
        acc[6] = fmaf(w, f3.x, acc[6]); acc[7] = fmaf(w, f3.y, acc[7]);
    }

    __shared__ float part[2][64][8];
    #pragma unroll
    for (int j = 0; j < 8; j++) part[so][th][j] = acc[j];
    __syncthreads();
    if (so == 0) {
        float4 o0, o1;
        o0.x = acc[0] + part[1][th][0]; o0.y = acc[1] + part[1][th][1];
        o0.z = acc[2] + part[1][th][2]; o0.w = acc[3] + part[1][th][3];
        o1.x = acc[4] + part[1][th][4]; o1.y = acc[5] + part[1][th][5];
        o1.z = acc[6] + part[1][th][6]; o1.w = acc[7] + part[1][th][7];
        float* d = g_ctx_part + ((size_t)(sc * B_DIM + b)) * H_DIM + h8;
        *(float4*)(d)     = o0;
        *(float4*)(d + 4) = o1;
    }
}

__global__ void __launch_bounds__(256)
context_reduce_kernel(float* __restrict__ context)
{
    const int i = blockIdx.x * blockDim.x + threadIdx.x;
    float s = 0.f;
    #pragma unroll
    for (int n = 0; n < SCHUNK; n++)
        s += g_ctx_part[(size_t)n * (B_DIM * H_DIM) + i];
    context[i] = s;
}

// ---------------------------------------------------------------------------
extern "C" void kernel_launch(void* const* d_in, const int* in_sizes, int n_in,
                              void* d_out, int out_size)
{
    (void)in_sizes; (void)n_in; (void)out_size;
    const float* hidden = (const float*)d_in[0];
    const int*   mask   = (const int*)d_in[1];
    const float* W      = (const float*)d_in[2];
    const float* bias   = (const float*)d_in[3];
    const float* v      = (const float*)d_in[4];

    float* context = (float*)d_out;                          // [B, H]
    float* weights = (float*)d_out + (size_t)B_DIM * H_DIM;  // [B, S]

    cudaFuncSetAttribute(scores_gemm_mma,
                         cudaFuncAttributeMaxDynamicSharedMemorySize, GEMM_SMEM);

    convert_wx_kernel<<<NTILES * NKCH + NMTILES * NKCH, 256>>>(W, hidden);

    scores_gemm_mma<<<dim3(NTILES, NMTILES), 512, GEMM_SMEM>>>(bias, v);

    softmax_kernel<<<B_DIM, 256>>>(mask, weights);

    context_part_kernel<<<dim3(SCHUNK, B_DIM), 128>>>(weights);
    context_reduce_kernel<<<(B_DIM * H_DIM) / 256, 256>>>(context);
}

// round 17
// speedup vs baseline: 1.1563x; 1.1563x over previous
#include <cuda_runtime.h>
#include <cuda_bf16.h>
#include <cuda_fp16.h>
#include <cstdint>

// ---------------------------------------------------------------------------
// Problem dims
// ---------------------------------------------------------------------------
#define B_DIM 64
#define S_DIM 2048
#define H_DIM 512
#define M_DIM (B_DIM * S_DIM)   // 131072
#define NEG_INF_SCORE (-1e9f)

// GEMM tiling: CTA 128x128, K chunks of 64, 16 warps (4m x 4n), warp 32x32
#define KC 64
#define NKCH (H_DIM / KC)        // 8
#define MT 128
#define NT 128
#define NTILES (H_DIM / NT)      // 4
#define NMTILES (M_DIM / MT)     // 1024
#define NSTAGE 3

// SMEM stage layout (bytes): A fp16 16KB, B fp16 16KB
#define A_OFF 0
#define B_OFF 16384
#define STAGE 32768
#define GEMM_SMEM (NSTAGE * STAGE)   // 96 KB -> 2 CTAs/SM

// Context s-chunking
#define SCHUNK 32
#define S_PER_CHUNK (S_DIM / SCHUNK)  // 64

// ---------------------------------------------------------------------------
// Device scratch (static only).
// g_Wh / g_Xh: fp16 pre-swizzled tiles, 128 rows x 64 k each, 16 KB,
// SW128-swizzled 128B rows. X tile (t, c) at index (t*8 + c).
// ---------------------------------------------------------------------------
__device__ __align__(16) __half g_Wh[H_DIM * H_DIM];
__device__ __align__(16) __half g_Xh[(size_t)M_DIM * H_DIM];   // 128 MB
__device__ float g_score_part[NTILES * M_DIM];
__device__ __align__(16) float g_ctx_part[SCHUNK * B_DIM * H_DIM];

__device__ __forceinline__ uint32_t smem_u32(const void* p) {
    uint32_t a;
    asm("{ .reg .u64 t; cvta.to.shared.u64 t, %1; cvt.u32.u64 %0, t; }" : "=r"(a) : "l"(p));
    return a;
}
// SW128 swizzle of (row-byte-base, column-byte-offset<128). Exact and in-bounds.
__device__ __forceinline__ uint32_t swz(uint32_t rowoff, uint32_t col) {
    return rowoff + (col ^ ((rowoff >> 3) & 0x70));
}

__device__ __forceinline__ void cp_async16(uint32_t dst, const void* src) {
    asm volatile("cp.async.cg.shared.global [%0], [%1], 16;"
                 :: "r"(dst), "l"(__cvta_generic_to_global(src)) : "memory");
}
__device__ __forceinline__ void cp_async_commit() {
    asm volatile("cp.async.commit_group;" ::: "memory");
}

__device__ __forceinline__ void ldsm_x4(uint32_t* r, uint32_t addr) {
    asm volatile("ldmatrix.sync.aligned.m8n8.x4.shared.b16 {%0,%1,%2,%3}, [%4];"
                 : "=r"(r[0]), "=r"(r[1]), "=r"(r[2]), "=r"(r[3]) : "r"(addr));
}

__device__ __forceinline__ void mma16816(float* d, const uint32_t* a, uint32_t b0, uint32_t b1) {
    asm volatile(
        "mma.sync.aligned.m16n8k16.row.col.f32.f16.f16.f32 "
        "{%0,%1,%2,%3}, {%4,%5,%6,%7}, {%8,%9}, {%0,%1,%2,%3};"
        : "+f"(d[0]), "+f"(d[1]), "+f"(d[2]), "+f"(d[3])
        : "r"(a[0]), "r"(a[1]), "r"(a[2]), "r"(a[3]), "r"(b0), "r"(b1));
}

// pack 2 floats -> one fp16x2 register
__device__ __forceinline__ uint32_t pack_h2(float x, float y) {
    __half2 h = __floats2half2_rn(x, y);
    return *reinterpret_cast<uint32_t*>(&h);
}

// ---------------------------------------------------------------------------
// Combined pre-convert: W (blocks 0..31) and X (blocks 32..32+8191) ->
// pre-swizzled fp16 tiles. 256 threads.
// Fully-coalesced mapping: 16 consecutive threads read one row-chunk's 256B
// contiguously (row = i*16 + tid>>4, kcol = (tid&15)*4); the same 16 threads
// emit one full 128B swizzled fp16 line.
// ---------------------------------------------------------------------------
__global__ void __launch_bounds__(256)
convert_wx_kernel(const float* __restrict__ W, const float* __restrict__ X)
{
    const int id  = blockIdx.x;
    const int tid = threadIdx.x;
    const int rsub = tid >> 4;             // 0..15 (row subgroup)
    const int kc4  = (tid & 15) * 4;       // k element offset (4 elems)

    const float* src;
    char* dst;
    if (id < NTILES * NKCH) {              // W tile (nt, c)
        const int nt = id >> 3;
        const int c  = id & 7;
        src = W + (size_t)(nt * NT) * H_DIM + c * KC;
        dst = (char*)g_Wh + (size_t)id * 16384;
    } else {                               // X tile (t, c)
        const int idx = id - NTILES * NKCH;
        const int t = idx >> 3;
        const int c = idx & 7;
        src = X + (size_t)(t * MT) * H_DIM + c * KC;
        dst = (char*)g_Xh + (size_t)idx * 16384;
    }

    #pragma unroll
    for (int i = 0; i < 8; i++) {
        const int row = i * 16 + rsub;
        float4 xv = *(const float4*)(src + (size_t)row * H_DIM + kc4);
        uint2 hv;
        hv.x = pack_h2(xv.x, xv.y);
        hv.y = pack_h2(xv.z, xv.w);
        const uint32_t off = swz((uint32_t)row * 128, (uint32_t)(kc4 * 2));
        *(uint2*)(dst + off) = hv;
    }
}

// ---------------------------------------------------------------------------
// Scores GEMM via mma.sync fp16 (single term, fp32 accum), fused tanh.v
// reduce. A and B both pre-converted fp16, pure cp.async mainloop.
// grid (4 n-tiles, 1024 m-tiles) nt-fast for X L2 reuse.
// 512 threads / 16 warps, 3-stage pipeline, 2 CTAs/SM.
// ---------------------------------------------------------------------------
__global__ void __launch_bounds__(512, 2)
scores_gemm_mma(const float* __restrict__ bias,
                const float* __restrict__ v)
{
    extern __shared__ char smem[];
    __shared__ float red[4][MT];

    const uint32_t sb = smem_u32(smem);
    const int tid  = threadIdx.x;
    const int wid  = tid >> 5;
    const int lane = tid & 31;
    const int wm   = wid & 3;      // warp m index (0..3)
    const int wn   = wid >> 2;     // warp n index (0..3)
    const int nt = blockIdx.x;     // n-tile (fast dim -> adjacent CTAs share X)
    const int t  = blockIdx.y;     // m-tile

    // A/B global tiles (pre-swizzled 16KB blobs)
    const char* ag = (const char*)g_Xh + (size_t)(t * NKCH) * 16384;
    const char* bg = (const char*)g_Wh + (size_t)(nt * NKCH) * 16384;

    // ldmatrix row bases; column = kb + ks*32 composed inside the swizzle
    const int lrow = lane & 15;
    const uint32_t kb = (lane >> 4) * 16;
    uint32_t a_rowb[2], b_rowb[2];
    #pragma unroll
    for (int mi = 0; mi < 2; mi++)
        a_rowb[mi] = (uint32_t)(wm * 32 + mi * 16 + lrow) * 128;
    #pragma unroll
    for (int np = 0; np < 2; np++)
        b_rowb[np] = (uint32_t)(wn * 32 + np * 16 + lrow) * 128;

    float acc[2][4][4];
    #pragma unroll
    for (int mi = 0; mi < 2; mi++)
        #pragma unroll
        for (int ni = 0; ni < 4; ni++)
            #pragma unroll
            for (int j = 0; j < 4; j++) acc[mi][ni][j] = 0.f;

    // cp.async A+B for chunk c into stage c%3 (one commit group per chunk)
    auto ab_load = [&](int c) {
        const uint32_t stb = sb + (uint32_t)(c % NSTAGE) * STAGE;
        const char* ah = ag + (size_t)c * 16384;
        const char* bh = bg + (size_t)c * 16384;
        #pragma unroll
        for (int it = 0; it < 2; it++) {
            cp_async16(stb + A_OFF + tid * 16 + it * 8192, ah + tid * 16 + it * 8192);
            cp_async16(stb + B_OFF + tid * 16 + it * 8192, bh + tid * 16 + it * 8192);
        }
        cp_async_commit();
    };

    // ---- prologue: chunks 0, 1 ----
    ab_load(0);
    ab_load(1);

    for (int c = 0; c < NKCH; c++) {
        if (c == NKCH - 1) asm volatile("cp.async.wait_group 0;" ::: "memory");
        else               asm volatile("cp.async.wait_group 1;" ::: "memory");
        __syncthreads();

        if (c + 2 < NKCH)
            ab_load(c + 2);     // async, overlaps compute below; stage free

        // ---- compute chunk c ----
        const uint32_t st = sb + (uint32_t)(c % NSTAGE) * STAGE;
        #pragma unroll
        for (int ks = 0; ks < KC / 16; ks++) {
            const uint32_t kcol = kb + ks * 32;   // < 128, composed into swizzle
            uint32_t ah[2][4], bh[2][4];
            #pragma unroll
            for (int mi = 0; mi < 2; mi++)
                ldsm_x4(ah[mi], st + A_OFF + swz(a_rowb[mi], kcol));
            #pragma unroll
            for (int np = 0; np < 2; np++)
                ldsm_x4(bh[np], st + B_OFF + swz(b_rowb[np], kcol));
            #pragma unroll
            for (int mi = 0; mi < 2; mi++)
                #pragma unroll
                for (int np = 0; np < 2; np++)
                    #pragma unroll
                    for (int hf = 0; hf < 2; hf++)
                        mma16816(acc[mi][np * 2 + hf], ah[mi],
                                 bh[np][hf], bh[np][hf + 2]);
        }
    }

    // ---- epilogue: rsum[row] = sum_n v[n]*tanh(acc + b[n]) ----
    const int ncol0 = nt * NT + wn * 32 + (lane & 3) * 2;
    float rs[2][2] = {{0.f, 0.f}, {0.f, 0.f}};
    #pragma unroll
    for (int np = 0; np < 2; np++) {
        #pragma unroll
        for (int hf = 0; hf < 2; hf++) {
            #pragma unroll
            for (int cc = 0; cc < 2; cc++) {
                const int col = ncol0 + np * 16 + hf * 8 + cc;
                const float bb = bias[col];
                const float vv = v[col];
                #pragma unroll
                for (int mi = 0; mi < 2; mi++) {
                    float x0 = acc[mi][np * 2 + hf][cc] + bb;       // row groupID
                    float x1 = acc[mi][np * 2 + hf][cc + 2] + bb;   // row groupID+8
                    float t0, t1;
                    asm("tanh.approx.f32 %0, %1;" : "=f"(t0) : "f"(x0));
                    asm("tanh.approx.f32 %0, %1;" : "=f"(t1) : "f"(x1));
                    rs[mi][0] = fmaf(t0, vv, rs[mi][0]);
                    rs[mi][1] = fmaf(t1, vv, rs[mi][1]);
                }
            }
        }
    }
    // reduce across the 4 lanes sharing a row (lane bits 0-1)
    #pragma unroll
    for (int mi = 0; mi < 2; mi++)
        #pragma unroll
        for (int h = 0; h < 2; h++) {
            rs[mi][h] += __shfl_xor_sync(0xffffffffu, rs[mi][h], 1);
            rs[mi][h] += __shfl_xor_sync(0xffffffffu, rs[mi][h], 2);
        }

    __syncthreads();   // all compute done before red[] use
    if ((lane & 3) == 0) {
        #pragma unroll
        for (int mi = 0; mi < 2; mi++)
            #pragma unroll
            for (int h = 0; h < 2; h++)
                red[wn][wm * 32 + mi * 16 + h * 8 + (lane >> 2)] = rs[mi][h];
    }
    __syncthreads();
    if (tid < MT) {
        float s = red[0][tid] + red[1][tid] + red[2][tid] + red[3][tid];
        g_score_part[(size_t)nt * M_DIM + (size_t)t * MT + tid] = s;
    }
}

// ---------------------------------------------------------------------------
// Softmax (folds 4 n-tile partials), mask as int32
// ---------------------------------------------------------------------------
__device__ __forceinline__ float warp_max(float v) {
    #pragma unroll
    for (int o = 16; o > 0; o >>= 1) v = fmaxf(v, __shfl_xor_sync(0xffffffffu, v, o));
    return v;
}
__device__ __forceinline__ float warp_sum(float v) {
    #pragma unroll
    for (int o = 16; o > 0; o >>= 1) v += __shfl_xor_sync(0xffffffffu, v, o);
    return v;
}

__global__ void __launch_bounds__(256)
softmax_kernel(const int* __restrict__ mask, float* __restrict__ weights)
{
    const int b    = blockIdx.x;
    const int tid  = threadIdx.x;
    const int lane = tid & 31;
    const int wid  = tid >> 5;

    __shared__ float red[8];

    float vals[8];
    float mx = -3.4e38f;
    #pragma unroll
    for (int i = 0; i < 8; i++) {
        const size_t m = (size_t)b * S_DIM + tid + i * 256;
        float sc = 0.f;
        #pragma unroll
        for (int n = 0; n < NTILES; n++)
            sc += g_score_part[(size_t)n * M_DIM + m];
        if (mask[m] == 0) sc = NEG_INF_SCORE;
        vals[i] = sc;
        mx = fmaxf(mx, sc);
    }

    mx = warp_max(mx);
    if (lane == 0) red[wid] = mx;
    __syncthreads();
    float bmax = red[0];
    #pragma unroll
    for (int i = 1; i < 8; i++) bmax = fmaxf(bmax, red[i]);
    __syncthreads();

    float s_sum = 0.f;
    #pragma unroll
    for (int i = 0; i < 8; i++) {
        vals[i] = __expf(vals[i] - bmax);
        s_sum += vals[i];
    }
    s_sum = warp_sum(s_sum);
    if (lane == 0) red[wid] = s_sum;
    __syncthreads();
    float total = red[0];
    #pragma unroll
    for (int i = 1; i < 8; i++) total += red[i];

    const float inv = 1.0f / total;
    #pragma unroll
    for (int i = 0; i < 8; i++)
        weights[(size_t)b * S_DIM + tid + i * 256] = vals[i] * inv;
}

// ---------------------------------------------------------------------------
// Context: weighted sum over S, reading the pre-converted fp16 X tiles
// (halves DRAM traffic vs fp32 hidden). Block (sc, b), 128 threads.
// ---------------------------------------------------------------------------
__global__ void __launch_bounds__(128)
context_part_kernel(const float* __restrict__ weights)
{
    const int sc = blockIdx.x;          // 0..31
    const int b  = blockIdx.y;          // 0..63
    const int tid = threadIdx.x;
    const int th  = tid & 63;
    const int so  = tid >> 6;           // 0..1
    const int h8  = th * 8;             // h offset, step 8
    const int c   = h8 >> 6;            // k-chunk 0..7
    const uint32_t colb = (uint32_t)((h8 & 63) * 2);   // 0..112, 16B aligned

    const float* wrow = weights + (size_t)b * S_DIM + sc * S_PER_CHUNK;

    float acc[8];
    #pragma unroll
    for (int j = 0; j < 8; j++) acc[j] = 0.f;

    for (int i = so; i < S_PER_CHUNK; i += 2) {
        const int m   = b * S_DIM + sc * S_PER_CHUNK + i;
        const int t   = m >> 7;
        const int row = m & 127;
        const char* tile = (const char*)g_Xh + ((size_t)(t * NKCH + c)) * 16384;
        uint4 hv = *(const uint4*)(tile + swz((uint32_t)row * 128, colb));
        const float w = wrow[i];

        float2 f0 = __half22float2(*reinterpret_cast<__half2*>(&hv.x));
        float2 f1 = __half22float2(*reinterpret_cast<__half2*>(&hv.y));
        float2 f2 = __half22float2(*reinterpret_cast<__half2*>(&hv.z));
        float2 f3 = __half22float2(*reinterpret_cast<__half2*>(&hv.w));
        acc[0] = fmaf(w, f0.x, acc[0]); acc[1] = fmaf(w, f0.y, acc[1]);
        acc[2] = fmaf(w, f1.x, acc[2]); acc[3] = fmaf(w, f1.y, acc[3]);
        acc[4] = fmaf(w, f2.x, acc[4]); acc[5] = fmaf(w, f2.y, acc[5]);
        acc[6] = fmaf(w, f3.x, acc[6]); acc[7] = fmaf(w, f3.y, acc[7]);
    }

    __shared__ float part[2][64][8];
    #pragma unroll
    for (int j = 0; j < 8; j++) part[so][th][j] = acc[j];
    __syncthreads();
    if (so == 0) {
        float4 o0, o1;
        o0.x = acc[0] + part[1][th][0]; o0.y = acc[1] + part[1][th][1];
        o0.z = acc[2] + part[1][th][2]; o0.w = acc[3] + part[1][th][3];
        o1.x = acc[4] + part[1][th][4]; o1.y = acc[5] + part[1][th][5];
        o1.z = acc[6] + part[1][th][6]; o1.w = acc[7] + part[1][th][7];
        float* d = g_ctx_part + ((size_t)(sc * B_DIM + b)) * H_DIM + h8;
        *(float4*)(d)     = o0;
        *(float4*)(d + 4) = o1;
    }
}

__global__ void __launch_bounds__(256)
context_reduce_kernel(float* __restrict__ context)
{
    const int i = blockIdx.x * blockDim.x + threadIdx.x;
    float s = 0.f;
    #pragma unroll
    for (int n = 0; n < SCHUNK; n++)
        s += g_ctx_part[(size_t)n * (B_DIM * H_DIM) + i];
    context[i] = s;
}

// ---------------------------------------------------------------------------
extern "C" void kernel_launch(void* const* d_in, const int* in_sizes, int n_in,
                              void* d_out, int out_size)
{
    (void)in_sizes; (void)n_in; (void)out_size;
    const float* hidden = (const float*)d_in[0];
    const int*   mask   = (const int*)d_in[1];
    const float* W      = (const float*)d_in[2];
    const float* bias   = (const float*)d_in[3];
    const float* v      = (const float*)d_in[4];

    float* context = (float*)d_out;                          // [B, H]
    float* weights = (float*)d_out + (size_t)B_DIM * H_DIM;  // [B, S]

    cudaFuncSetAttribute(scores_gemm_mma,
                         cudaFuncAttributeMaxDynamicSharedMemorySize, GEMM_SMEM);

    convert_wx_kernel<<<NTILES * NKCH + NMTILES * NKCH, 256>>>(W, hidden);

    scores_gemm_mma<<<dim3(NTILES, NMTILES), 512, GEMM_SMEM>>>(bias, v);

    softmax_kernel<<<B_DIM, 256>>>(mask, weights);

    context_part_kernel<<<dim3(SCHUNK, B_DIM), 128>>>(weights);
    context_reduce_kernel<<<(B_DIM * H_DIM) / 256, 256>>>(context);
}